// round 8
// baseline (speedup 1.0000x reference)
#include <cuda_runtime.h>

#define RES 30
#define NI 32
#define NC 32
#define NPTS (NI * NC)       // 1024
#define GRID_PTS (RES * RES) // 900
#define NTHREADS 960
#define SETSZ 240            // 30 iy * 8 ix-chunks
#define KPT 4                // grid points per thread

// exp(-200*m) == exp2(KS2*m),  KS2 = -200 * log2(e)
#define KS2 (-288.53900817779268f)

typedef unsigned long long ull;

__device__ __forceinline__ ull pk2(float lo, float hi) {
    ull r; asm("mov.b64 %0, {%1, %2};" : "=l"(r) : "f"(lo), "f"(hi)); return r;
}
__device__ __forceinline__ float2 unpk(ull v) {
    float2 r; asm("mov.b64 {%0, %1}, %2;" : "=f"(r.x), "=f"(r.y) : "l"(v)); return r;
}
__device__ __forceinline__ ull fma2(ull a, ull b, ull c) {
    ull r; asm("fma.rn.f32x2 %0, %1, %2, %3;" : "=l"(r) : "l"(a), "l"(b), "l"(c)); return r;
}
__device__ __forceinline__ float ex2f(float x) {
    float r; asm("ex2.approx.ftz.f32 %0, %1;" : "=f"(r) : "f"(x)); return r;
}

__global__ __launch_bounds__(NTHREADS, 1)
void persim_kernel(const float* __restrict__ births,
                   const float* __restrict__ deaths,
                   float* __restrict__ out) {
    const int s   = blockIdx.x;
    const int tid = threadIdx.x;

    __shared__ float4 xr[NPTS];        // {bx, dx, rb, rd}, r = px^2+py^2
    __shared__ float2 yv[NPTS];        // {by, dy}
    __shared__ float  axx[RES], axy[RES];
    __shared__ float  w2s[NI];
    __shared__ float  red[120];        // 30 warps * {mnx,mxx,mny,mxy}
    __shared__ float  slo[2], shi[2];
    __shared__ float  pacc[3][KPT][SETSZ]; // partials from quarters 1..3

    const float2* bp = (const float2*)(births + (size_t)s * NPTS * 2);
    const float2* dp = (const float2*)(deaths + (size_t)s * NPTS * 2);

    // ---- Phase 1: stage points + per-corner r, bbox reduction ----
    float mnx = 1e30f, mxx = -1e30f, mny = 1e30f, mxy = -1e30f;
    for (int p = tid; p < NPTS; p += NTHREADS) {
        float2 b = bp[p];
        float2 d = dp[p];
        float rb = fmaf(b.x, b.x, b.y * b.y);
        float rd = fmaf(d.x, d.x, d.y * d.y);
        xr[p] = make_float4(b.x, d.x, rb, rd);
        yv[p] = make_float2(b.y, d.y);
        mnx = fminf(mnx, fminf(b.x, d.x));
        mxx = fmaxf(mxx, fmaxf(b.x, d.x));
        mny = fminf(mny, fminf(b.y, d.y));
        mxy = fmaxf(mxy, fmaxf(b.y, d.y));
    }
#pragma unroll
    for (int o = 16; o; o >>= 1) {
        mnx = fminf(mnx, __shfl_xor_sync(0xffffffffu, mnx, o));
        mxx = fmaxf(mxx, __shfl_xor_sync(0xffffffffu, mxx, o));
        mny = fminf(mny, __shfl_xor_sync(0xffffffffu, mny, o));
        mxy = fmaxf(mxy, __shfl_xor_sync(0xffffffffu, mxy, o));
    }
    const int wid  = tid >> 5;
    const int lane = tid & 31;
    if (lane == 0) {
        red[wid * 4 + 0] = mnx;
        red[wid * 4 + 1] = mxx;
        red[wid * 4 + 2] = mny;
        red[wid * 4 + 3] = mxy;
    }
    __syncthreads();

    if (tid == 0) {
        float a = red[0], b = red[1], c = red[2], d = red[3];
#pragma unroll
        for (int w = 1; w < 30; w++) {
            a = fminf(a, red[w * 4 + 0]);
            b = fmaxf(b, red[w * 4 + 1]);
            c = fminf(c, red[w * 4 + 2]);
            d = fmaxf(d, red[w * 4 + 3]);
        }
        float mgx = 0.1f * (b - a);
        float mgy = 0.1f * (d - c);
        slo[0] = a - mgx; shi[0] = b + mgx;
        slo[1] = c - mgy; shi[1] = d + mgy;
    }
    // interval weights (warp 1), overlapped with bbox finalize
    if (tid >= 32 && tid < 64) {
        int i = tid - 32;
        float sum = 0.0f;
#pragma unroll 8
        for (int c = 0; c < NC; c++) {
            float4 P = xr[i * NC + c];
            float2 Y = yv[i * NC + c];
            sum += fmaxf(fabsf(P.y - P.x), fabsf(Y.y - Y.x));
        }
        float w = sum * (1.0f / NC);
        w2s[i] = w * w;
    }
    __syncthreads();

    if (tid < RES) {
        float t = (float)tid * (1.0f / (RES - 1));
        axx[tid] = slo[0] + t * (shi[0] - slo[0]);
        axy[tid] = slo[1] + t * (shi[1] - slo[1]);
    }
    __syncthreads();

    // ---- Phase 2: KDE. 4 warp-sets (quarters) split the interval loop:
    // quarter q handles i = q*8 .. q*8+7. Each set: 240 threads =
    // 30 iy columns x 8 ix-chunks, up to 4 grid points per thread.
    //
    // dist^2 = gx^2+gy^2 + (r - 2*gx*px - 2*gy*py); min over corners of the
    // bracket (g-part constant per thread), gx^2+gy^2 folded into exp arg.
    const int quarter = tid / SETSZ;
    const int t       = tid % SETSZ;
    const int iy      = t >> 3;
    const int chunk   = t & 7;

    const float gy = axy[iy];
    const ull n2gy = pk2(-2.0f * gy, -2.0f * gy);

    ull   n2gx[KPT];
    float ks2g2[KPT];
#pragma unroll
    for (int k = 0; k < KPT; k++) {
        int ix = chunk + 8 * k;
        float gx = (ix < RES) ? axx[ix] : 0.0f;
        n2gx[k]  = pk2(-2.0f * gx, -2.0f * gx);
        ks2g2[k] = KS2 * fmaf(gx, gx, gy * gy);
    }

    float acc[KPT];
#pragma unroll
    for (int k = 0; k < KPT; k++) acc[k] = 0.0f;

    const int i0 = quarter * 8;
    const ulonglong2* xp = ((const ulonglong2*)xr) + i0 * NC;
    const ull*        yp = ((const ull*)yv) + i0 * NC;

    for (int i = 0; i < 8; i++) {
        float minb[KPT], mind[KPT];
#pragma unroll
        for (int k = 0; k < KPT; k++) { minb[k] = 1e30f; mind[k] = 1e30f; }

#pragma unroll 8
        for (int c = 0; c < NC; c++) {
            ulonglong2 P = xp[i * NC + c];       // x=(bx,dx), y=(rb,rd)
            ull ypair    = yp[i * NC + c];       // (by,dy)
            ull tpair = fma2(ypair, n2gy, P.y);  // r - 2gy*py
#pragma unroll
            for (int k = 0; k < KPT; k++) {
                ull m = fma2(P.x, n2gx[k], tpair); // r - 2g.p
                float2 mf = unpk(m);
                minb[k] = fminf(minb[k], mf.x);
                mind[k] = fminf(mind[k], mf.y);
            }
        }

        float wv = w2s[i0 + i];
#pragma unroll
        for (int k = 0; k < KPT; k++) {
            float mm  = fmaxf(minb[k], mind[k]);
            float arg = fmaf(KS2, mm, ks2g2[k]);   // KS2*(g2 + bracket)
            acc[k] = fmaf(wv, ex2f(arg), acc[k]);
        }
    }

    // quarters 1-3 publish partials
    if (quarter != 0) {
#pragma unroll
        for (int k = 0; k < KPT; k++) pacc[quarter - 1][k][t] = acc[k];
    }
    __syncthreads();

    if (quarter == 0) {
        float* orow = out + (size_t)s * GRID_PTS;
#pragma unroll
        for (int k = 0; k < KPT; k++) {
            int ix = chunk + 8 * k;
            if (ix < RES) {
                float v = acc[k] + pacc[0][k][t] + pacc[1][k][t] + pacc[2][k][t];
                orow[ix * RES + iy] = v;
            }
        }
    }
}

extern "C" void kernel_launch(void* const* d_in, const int* in_sizes, int n_in,
                              void* d_out, int out_size) {
    const float* births = (const float*)d_in[0];
    const float* deaths = (const float*)d_in[1];
    float* out = (float*)d_out;
    int S = in_sizes[0] / (NPTS * 2);   // 128 for the reference shapes
    persim_kernel<<<S, NTHREADS>>>(births, deaths, out);
}